// round 15
// baseline (speedup 1.0000x reference)
#include <cuda_runtime.h>
#include <math.h>

// NTXentLoss: B=2048, P=16, N=128, D=512 (fp32).
// R15: TWO anchors per block (grid 1024). Warps 0-3 own anchor 2b, warps 4-7
//      own 2b+1. Shared prologue (one mask pass, one target pass), R8
//      pipelined streaming per 4-warp group, PARALLEL single-warp epilogues
//      (warp 0 / warp 4). Halves per-anchor serial overhead; bytes unchanged.

#define DDIM 512
#define D4 (DDIM / 4)
#define THREADS 256
#define NWARPS 8
#define HWARPS 4               // warps per anchor
#define TEMP_INV 10.0f
#define COS_EPS 1e-8f

// scratch (no cudaMalloc allowed)
__device__ float g_loss[4096];
__device__ unsigned int g_count = 0;

__device__ __forceinline__ float warpReduceSum(float v) {
#pragma unroll
    for (int o = 16; o; o >>= 1) v += __shfl_down_sync(0xffffffffu, v, o);
    return v;
}

__device__ __forceinline__ float warpAllSum(float v) {
#pragma unroll
    for (int o = 16; o; o >>= 1) v += __shfl_xor_sync(0xffffffffu, v, o);
    return v;
}

__device__ __forceinline__ float warpAllMax(float v) {
#pragma unroll
    for (int o = 16; o; o >>= 1) v = fmaxf(v, __shfl_xor_sync(0xffffffffu, v, o));
    return v;
}

__global__ void __launch_bounds__(THREADS, 5)
ntxent_main_kernel(const float* __restrict__ target,
                   const float* __restrict__ positives,
                   const float* __restrict__ negatives,
                   const int* __restrict__ pos_idx,
                   const int* __restrict__ neg_mask,
                   float* __restrict__ out,
                   int B, int P, int N) {
    const int tid = threadIdx.x;
    const int lane = tid & 31;
    const int w = tid >> 5;
    const int half = w >> 2;          // which anchor this warp serves (0/1)
    const int wl = w & 3;             // warp index within the anchor group
    const int b = 2 * blockIdx.x + half;

    __shared__ float4 s_tgt[2][D4];   // two target rows (4KB)
    __shared__ float s_dot[2][132];   // per-anchor row dots ([M]=pos)
    __shared__ float s_q[2][132];
    __shared__ int   s_valid[2][132];
    __shared__ int   s_wcnt[NWARPS];

    // --- mask pass: warp w covers rows 32*(w&3).. of anchor (w>>2) ---
    const int row = tid & 127;        // row within this anchor's mask
    int mvalid = (neg_mask[(size_t)b * N + row] != 0);
    unsigned bal = __ballot_sync(0xffffffffu, mvalid);
    if (lane == 0) s_wcnt[w] = __popc(bal);

    // --- target pass: tid<128 -> anchor A, tid>=128 -> anchor B ---
    s_tgt[half][row] = ((const float4*)(target + (size_t)b * DDIM))[row];
    const int pi = pos_idx[b];
    __syncthreads();   // s_tgt + s_wcnt ready

    // per-half compaction offsets
    int off = 0, M = 0;
#pragma unroll
    for (int j = 0; j < HWARPS; j++) {
        int c = s_wcnt[half * HWARPS + j];
        if (j < wl) off += c;
        M += c;
    }
    if (mvalid) s_valid[half][off + __popc(bal & ((1u << lane) - 1u))] = row;
    __syncthreads();   // s_valid ready

    // --- software-pipelined row streaming (R8 loop, per 4-warp group) ---
    const float4* negb = (const float4*)(negatives + (size_t)b * (size_t)N * DDIM);
    const float4* posr = (const float4*)(positives + ((size_t)b * P + pi) * (size_t)DDIM);
    const float4* tg = s_tgt[half];
    const int* vlist = s_valid[half];
    float* dotv = s_dot[half];
    float* qv = s_q[half];
    const int R = M + 1;

    int i = wl;
    if (i < R) {
        const float4* vc = (i < M) ? (negb + (size_t)vlist[i] * D4) : posr;
        float4 cur[4];
#pragma unroll
        for (int k = 0; k < 4; k++) cur[k] = vc[lane + 32 * k];

        for (; i < R; i += HWARPS) {
            const int j = i + HWARPS;
            const float4* vn = (j < R) ? ((j < M) ? (negb + (size_t)vlist[j] * D4) : posr)
                                       : vc;
            float4 nxt[4];
#pragma unroll
            for (int k = 0; k < 4; k++) nxt[k] = vn[lane + 32 * k];

            float dot = 0.0f, q = 0.0f;
#pragma unroll
            for (int k = 0; k < 4; k++) {
                float4 t = tg[lane + 32 * k];
                dot = fmaf(cur[k].x, t.x, dot); dot = fmaf(cur[k].y, t.y, dot);
                dot = fmaf(cur[k].z, t.z, dot); dot = fmaf(cur[k].w, t.w, dot);
                q = fmaf(cur[k].x, cur[k].x, q); q = fmaf(cur[k].y, cur[k].y, q);
                q = fmaf(cur[k].z, cur[k].z, q); q = fmaf(cur[k].w, cur[k].w, q);
            }
            dot = warpReduceSum(dot);
            q = warpReduceSum(q);
            if (lane == 0) { dotv[i] = dot; qv[i] = q; }

#pragma unroll
            for (int k = 0; k < 4; k++) cur[k] = nxt[k];
            vc = vn;
        }
    }
    __syncthreads();   // ONLY epilogue barrier

    // --- parallel single-warp epilogues: warp 0 -> anchor A, warp 4 -> B ---
    if (wl == 0) {
        // ||t||^2 from SMEM (resident)
        float tq = 0.0f;
#pragma unroll
        for (int k = 0; k < 4; k++) {
            float4 t = tg[lane + 32 * k];
            tq = fmaf(t.x, t.x, tq); tq = fmaf(t.y, t.y, tq);
            tq = fmaf(t.z, t.z, tq); tq = fmaf(t.w, t.w, tq);
        }
        const float tnorm = sqrtf(warpAllSum(tq));

        // convert rows to logits in place: dotv[r] <- sim(r)
        float mx = -INFINITY;
        for (int r = lane; r < R; r += 32) {
            float sim = (dotv[r] / fmaxf(sqrtf(qv[r]) * tnorm, COS_EPS)) * TEMP_INV;
            dotv[r] = sim;
            mx = fmaxf(mx, sim);
        }
        __syncwarp();
        mx = warpAllMax(mx);

        float e = 0.0f;
        for (int r = lane; r < R; r += 32) e += expf(dotv[r] - mx);
        e = warpAllSum(e);
        const float pos_sim = dotv[M];

        // publish; last finisher computes the mean
        int islast = 0;
        if (lane == 0) {
            g_loss[b] = logf(e) + mx - pos_sim;
            __threadfence();
            unsigned int old = atomicAdd(&g_count, 1u);
            islast = (old == (unsigned int)(B - 1));
        }
        islast = __shfl_sync(0xffffffffu, islast, 0);
        if (islast) {
            __threadfence();
            float v = 0.0f;
            for (int k = lane; k < B; k += 32) v += g_loss[k];
            v = warpAllSum(v);
            if (lane == 0) {
                out[0] = v / (float)B;
                g_count = 0;  // reset for next graph replay
            }
        }
    }
}

extern "C" void kernel_launch(void* const* d_in, const int* in_sizes, int n_in,
                              void* d_out, int out_size) {
    const float* target = (const float*)d_in[0];
    const float* positives = (const float*)d_in[1];
    const float* negatives = (const float*)d_in[2];
    const int* pos_idx = (const int*)d_in[3];
    const int* neg_mask = (const int*)d_in[4];
    float* out = (float*)d_out;

    const int B = in_sizes[0] / DDIM;                 // 2048
    const int P = in_sizes[1] / in_sizes[0];          // 16
    const int N = in_sizes[2] / in_sizes[0];          // 128

    ntxent_main_kernel<<<B / 2, THREADS>>>(target, positives, negatives, pos_idx,
                                           neg_mask, out, B, P, N);
}